// round 11
// baseline (speedup 1.0000x reference)
#include <cuda_runtime.h>
#include <cstdint>

#define BB 64
#define TT 512
#define DD 1024
#define DKK 16
#define NEG_INF (-1e24f)

// scratch (device globals: allocation-free rule)
__device__ float g_q[BB * TT * DKK];
__device__ float g_k[BB * TT * DKK];
__device__ float g_y[(size_t)BB * TT * DD];
__device__ float g_wvT[DD * DD];
__device__ float g_xT[(size_t)BB * DD * TT];   // per-batch x^T, tf32-rounded

// ---------------------------------------------------------------------------
// helpers
// ---------------------------------------------------------------------------
__device__ __forceinline__ uint32_t smem_u32(const void* p) {
    uint32_t a;
    asm("{ .reg .u64 t; cvta.to.shared.u64 t, %1; cvt.u32.u64 %0, t; }"
        : "=r"(a) : "l"(p));
    return a;
}
__device__ __forceinline__ float to_tf32(float x) {
    uint32_t r;
    asm("cvt.rna.tf32.f32 %0, %1;" : "=r"(r) : "f"(x));
    return __uint_as_float(r);
}

#define CP_ASYNC16(dst_u32, src_ptr) \
    asm volatile("cp.async.cg.shared.global [%0], [%1], 16;" \
                 :: "r"(dst_u32), "l"(src_ptr) : "memory")
#define CP_COMMIT() asm volatile("cp.async.commit_group;" ::: "memory")
#define CP_WAIT(n)  asm volatile("cp.async.wait_group %0;" :: "n"(n) : "memory")

__device__ __forceinline__ void mma_tf32(float* d, const uint32_t* a, const uint32_t* b) {
    asm volatile(
        "mma.sync.aligned.m16n8k8.row.col.f32.tf32.tf32.f32 "
        "{%0,%1,%2,%3}, {%4,%5,%6,%7}, {%8,%9}, {%0,%1,%2,%3};"
        : "+f"(d[0]), "+f"(d[1]), "+f"(d[2]), "+f"(d[3])
        : "r"(a[0]), "r"(a[1]), "r"(a[2]), "r"(a[3]), "r"(b[0]), "r"(b[1]));
}

// ldmatrix: 8x8 b16 matrices == 8x4 fp32 tiles; lane -> (row l>>2, f32col l&3)
#define LDSM_X4(r0, r1, r2, r3, addr) \
    asm volatile("ldmatrix.sync.aligned.m8n8.x4.shared.b16 {%0,%1,%2,%3}, [%4];" \
                 : "=r"(r0), "=r"(r1), "=r"(r2), "=r"(r3) : "r"(addr))

// ---------------------------------------------------------------------------
// K0: WvT[n][k] = tf32(Wv[k][n])
// ---------------------------------------------------------------------------
__global__ void wvt_kernel(const float* __restrict__ Wv) {
    __shared__ float t[32][33];
    const int bx = blockIdx.x * 32, by = blockIdx.y * 32;
    const int tx = threadIdx.x, ty = threadIdx.y;
#pragma unroll
    for (int i = 0; i < 32; i += 8)
        t[ty + i][tx] = Wv[(size_t)(by + ty + i) * DD + bx + tx];
    __syncthreads();
#pragma unroll
    for (int i = 0; i < 32; i += 8)
        g_wvT[(size_t)(bx + ty + i) * DD + by + tx] = to_tf32(t[tx][ty + i]);
}

// ---------------------------------------------------------------------------
// K1: smem-GEMM qk + fused xT emission (unchanged from round 10)
// ---------------------------------------------------------------------------
#define QKR 128
#define QKC 64
#define QKPAD 68

__global__ void __launch_bounds__(256, 2)
qk_kernel(const float* __restrict__ x,
          const unsigned char* __restrict__ maskb,
          const float* __restrict__ Wq, const float* __restrict__ bq,
          const float* __restrict__ Wk, const float* __restrict__ bk) {
    __shared__ float xs[QKR * QKPAD];
    __shared__ float ws[QKC * 32];
    const uint32_t xs_u32 = smem_u32(xs);
    const uint32_t ws_u32 = smem_u32(ws);

    const int tid = threadIdx.x;
    const int r0  = blockIdx.x * QKR;
    const int b   = r0 / TT;
    const int sl0 = r0 % TT;

    const int tr = tid >> 3, tc = tid & 7;

    float acc[4][4];
#pragma unroll
    for (int j = 0; j < 4; j++) {
        const int c = tc * 4 + j;
        const float bias = (c < 16) ? bq[c] : bk[c - 16];
#pragma unroll
        for (int i = 0; i < 4; i++) acc[i][j] = bias;
    }

    const int ed   = tid >> 2;
    const int eseg = (tid & 3) * 32;

    for (int ch = 0; ch < 16; ch++) {
        const int k0 = ch * QKC;
        {
            const int kk = tid >> 2, c4 = tid & 3;
            CP_ASYNC16(ws_u32 + (kk * 32 + c4 * 4) * 4,
                       Wq + (size_t)(k0 + kk) * DKK + c4 * 4);
            CP_ASYNC16(ws_u32 + (kk * 32 + 16 + c4 * 4) * 4,
                       Wk + (size_t)(k0 + kk) * DKK + c4 * 4);
        }
#pragma unroll
        for (int it = 0; it < 8; it++) {
            const int idx = tid + it * 256;
            const int row = idx >> 4, c4 = idx & 15;
            CP_ASYNC16(xs_u32 + (row * QKPAD + c4 * 4) * 4,
                       x + (size_t)(r0 + row) * DD + k0 + c4 * 4);
        }
        CP_COMMIT();
        CP_WAIT(0);
        __syncthreads();

#pragma unroll 4
        for (int kk = 0; kk < QKC; kk++) {
            float a[4];
#pragma unroll
            for (int i = 0; i < 4; i++) a[i] = xs[(tr * 4 + i) * QKPAD + kk];
            const float4 w = *reinterpret_cast<const float4*>(&ws[kk * 32 + tc * 4]);
#pragma unroll
            for (int i = 0; i < 4; i++) {
                acc[i][0] += a[i] * w.x;
                acc[i][1] += a[i] * w.y;
                acc[i][2] += a[i] * w.z;
                acc[i][3] += a[i] * w.w;
            }
        }

        {
            float* dst = g_xT + (size_t)b * DD * TT + (size_t)(k0 + ed) * TT + sl0 + eseg;
#pragma unroll
            for (int j = 0; j < 8; j++) {
                float4 v;
                v.x = to_tf32(xs[(eseg + 4 * j + 0) * QKPAD + ed]);
                v.y = to_tf32(xs[(eseg + 4 * j + 1) * QKPAD + ed]);
                v.z = to_tf32(xs[(eseg + 4 * j + 2) * QKPAD + ed]);
                v.w = to_tf32(xs[(eseg + 4 * j + 3) * QKPAD + ed]);
                *reinterpret_cast<float4*>(dst + 4 * j) = v;
            }
        }
        __syncthreads();
    }

    int nz = 0;
#pragma unroll
    for (int p = 0; p < 64; p++)
        if (p & 3) nz |= maskb[p];
    const bool isBool = (nz != 0);

#pragma unroll
    for (int i = 0; i < 4; i++) {
        const int row = r0 + tr * 4 + i;
        const int mv = isBool ? (int)maskb[row]
                              : reinterpret_cast<const int*>(maskb)[row];
#pragma unroll
        for (int j = 0; j < 4; j++) {
            const int c = tc * 4 + j;
            if (c < 16) g_q[row * DKK + c] = acc[i][j];
            else        g_k[row * DKK + (c - 16)] = mv ? NEG_INF : acc[i][j];
        }
    }
}

// ---------------------------------------------------------------------------
// K2: scores + softmax + Y = P@x, causal skip + fragment double-buffering
// ---------------------------------------------------------------------------
#define PST 516
#define KS_STRIDE 17
#define BKP2 36
#define BBUF_FLOATS (128 * BKP2)                      // 4608
#define REGION_FLOATS (3 * BBUF_FLOATS)               // 13824
#define ATT_SMEM_FLOATS (64 * PST + REGION_FLOATS)    // 46848

__device__ __forceinline__ void ld_frags_a(uint32_t (*a)[4], uint32_t (*bf)[2],
                                           uint32_t aAddr0, uint32_t bBuf,
                                           int kb, int ksu) {
#pragma unroll
    for (int mt = 0; mt < 2; mt++)
        LDSM_X4(a[mt][0], a[mt][1], a[mt][2], a[mt][3],
                aAddr0 + (mt * 16 * PST + kb) * 4);
#pragma unroll
    for (int p = 0; p < 2; p++)
        LDSM_X4(bf[2 * p][0], bf[2 * p][1], bf[2 * p + 1][0], bf[2 * p + 1][1],
                bBuf + (p * 16 * BKP2 + ksu * 8) * 4);
}

__global__ void __launch_bounds__(256, 1)
attn_kernel() {
    extern __shared__ float sm[];
    __shared__ int s_flag;
    float* Ps = sm;
    float* rg = sm + 64 * PST;
    float* ks = rg;
    float* qs = rg + 512 * KS_STRIDE;
    const uint32_t ps_u32 = smem_u32(sm);
    const uint32_t rg_u32 = smem_u32(rg);

    const int b    = blockIdx.y;
    const int tile = blockIdx.x;
    const int tid  = threadIdx.x;
    const int qbase = b * TT + tile * 64;

    if (tid == 0) s_flag = 0;
    for (int i = tid; i < TT * DKK; i += 256) {
        int s = i >> 4, d = i & 15;
        ks[s * KS_STRIDE + d] = g_k[(b * TT + s) * DKK + d];
    }
    for (int i = tid; i < 64 * DKK; i += 256)
        qs[i] = g_q[qbase * DKK + i];
    __syncthreads();

    // ---- scores (only s < 64*(tile+1) computed; tail set to NEG_INF) ----
    {
        const int r  = tid >> 2;
        const int tq = tile * 64 + r;
        float qreg[16];
#pragma unroll
        for (int d = 0; d < 16; d++) qreg[d] = qs[r * 16 + d];
        const int s0 = tid & 3;
        const int jmax = 16 * (tile + 1);
        for (int j = 0; j < jmax; j++) {
            int s = s0 + 4 * j;
            float dot = 0.f;
#pragma unroll
            for (int d = 0; d < 16; d++) dot += qreg[d] * ks[s * KS_STRIDE + d];
            Ps[r * PST + s] = (s > tq) ? NEG_INF : dot * 4.0f;
        }
        for (int j = jmax; j < 128; j++)
            Ps[r * PST + s0 + 4 * j] = NEG_INF;
    }
    __syncthreads();

    // ---- softmax (write P as tf32); detect pathological rows ----
    {
        const int w = tid >> 5, l = tid & 31;
        for (int rr = 0; rr < 8; rr++) {
            const int r = w * 8 + rr;
            float v[16];
            float m = -3.4e38f;
#pragma unroll
            for (int i = 0; i < 16; i++) {
                v[i] = Ps[r * PST + l + 32 * i];
                m = fmaxf(m, v[i]);
            }
#pragma unroll
            for (int off = 16; off > 0; off >>= 1)
                m = fmaxf(m, __shfl_xor_sync(0xffffffffu, m, off));
            if (l == 0 && m < -1e20f) s_flag = 1;
            float ssum = 0.f;
#pragma unroll
            for (int i = 0; i < 16; i++) { v[i] = __expf(v[i] - m); ssum += v[i]; }
#pragma unroll
            for (int off = 16; off > 0; off >>= 1)
                ssum += __shfl_xor_sync(0xffffffffu, ssum, off);
            const float inv = 1.0f / ssum;
#pragma unroll
            for (int i = 0; i < 16; i++)
                Ps[r * PST + l + 32 * i] = to_tf32(v[i] * inv);
        }
    }
    __syncthreads();

    // ---- Y = P @ x via mma + ldmatrix, 3-stage, causal skip, dbuf frags ----
    const int wid = tid >> 5, lane = tid & 31;
    const int wm = (wid >> 2) * 32;
    const int wn = (wid & 3) * 32;
    const int lm = lane >> 2, lk = lane & 3;
    const int srow = tid >> 1;
    const int sc4  = (tid & 1) * 4;

    const int lr  = lane & 7;
    const int ah  = (lane >> 3) & 1;
    const int ac  = lane >> 4;
    const uint32_t aAddr0 = ps_u32 + ((wm + ah * 8 + lr) * PST + ac * 4) * 4;
    const uint32_t bAddrX4 = rg_u32 +
        ((wn + ((lane >> 4) & 1) * 8 + lr) * BKP2 + ((lane >> 3) & 1) * 4) * 4;

    const float* xTb = g_xT + (size_t)b * DD * TT;

    const int nch = s_flag ? 16 : 2 * (tile + 1);   // k-chunks per nb
    const int tot = 8 * nch;

#define PREF2(NB, KC, BUF) do {                                                      \
        uint32_t dstb = rg_u32 + ((BUF) * BBUF_FLOATS + srow * BKP2 + sc4 * 4) * 4;  \
        const float* src = xTb + (size_t)((NB) * 128 + srow) * TT + (KC) * 32 + sc4 * 4; \
        _Pragma("unroll")                                                            \
        for (int q = 0; q < 4; q++) CP_ASYNC16(dstb + q * 16, src + q * 4);          \
    } while (0)

    float acc[2][4][4];
#pragma unroll
    for (int i = 0; i < 2; i++)
#pragma unroll
        for (int j = 0; j < 4; j++)
#pragma unroll
            for (int r = 0; r < 4; r++) acc[i][j][r] = 0.f;

    int nbP = 0, kcP = 0;
    PREF2(nbP, kcP, 0); CP_COMMIT();
    if (++kcP == nch) { kcP = 0; nbP++; }
    PREF2(nbP, kcP, 1); CP_COMMIT();
    if (++kcP == nch) { kcP = 0; nbP++; }

    int nbC = 0, kcC = 0;
    for (int st = 0; st < tot; st++) {
        const int buf = st % 3;
        if (st + 2 < tot) { CP_WAIT(1); } else { CP_WAIT(0); }
        __syncthreads();
        if (st + 2 < tot) {
            PREF2(nbP, kcP, (st + 2) % 3); CP_COMMIT();
            if (++kcP == nch) { kcP = 0; nbP++; }
        }

        const uint32_t bBuf = bAddrX4 + buf * BBUF_FLOATS * 4;
        const int kbase = kcC * 32;

        uint32_t afr[2][2][4], bfr[2][4][2];
        ld_frags_a(afr[0], bfr[0], aAddr0, bBuf, kbase, 0);
#pragma unroll
        for (int ksu = 0; ksu < 4; ksu++) {
            const int cur = ksu & 1;
            if (ksu < 3)
                ld_frags_a(afr[cur ^ 1], bfr[cur ^ 1], aAddr0, bBuf,
                           kbase + (ksu + 1) * 8, ksu + 1);
#pragma unroll
            for (int mt = 0; mt < 2; mt++)
#pragma unroll
                for (int nt = 0; nt < 4; nt++)
                    mma_tf32(acc[mt][nt], afr[cur][mt], bfr[cur][nt]);
        }

        if (kcC == nch - 1) {
            const int nb = nbC * 128;
#pragma unroll
            for (int mt = 0; mt < 2; mt++) {
                const int row = qbase + wm + mt * 16 + lm;
#pragma unroll
                for (int nt = 0; nt < 4; nt++) {
                    const int col = nb + wn + nt * 8 + 2 * lk;
                    float2 v0 = { to_tf32(acc[mt][nt][0]), to_tf32(acc[mt][nt][1]) };
                    float2 v1 = { to_tf32(acc[mt][nt][2]), to_tf32(acc[mt][nt][3]) };
                    *reinterpret_cast<float2*>(g_y + (size_t)row * DD + col) = v0;
                    *reinterpret_cast<float2*>(g_y + (size_t)(row + 8) * DD + col) = v1;
#pragma unroll
                    for (int r = 0; r < 4; r++) acc[mt][nt][r] = 0.f;
                }
            }
        }
        if (++kcC == nch) { kcC = 0; nbC++; }
    }
#undef PREF2
}

// ---------------------------------------------------------------------------
// K3: out = Y @ WvT^T + bv, mma + ldmatrix, 3-stage, dbuf fragments
// ---------------------------------------------------------------------------
#define BM 128
#define BN 128
#define BK 32
#define BKP 36
#define TILE_FLOATS (BM * BKP)
#define GSTAGE_FLOATS (2 * TILE_FLOATS)
#define NSTAGE (DD / BK)

__device__ __forceinline__ void ld_frags_g(uint32_t (*a)[4], uint32_t (*bf)[2],
                                           uint32_t aBuf, uint32_t bBuf, int ksu) {
#pragma unroll
    for (int mt = 0; mt < 4; mt++)
        LDSM_X4(a[mt][0], a[mt][1], a[mt][2], a[mt][3],
                aBuf + (mt * 16 * BKP + ksu * 8) * 4);
#pragma unroll
    for (int p = 0; p < 2; p++)
        LDSM_X4(bf[2 * p][0], bf[2 * p][1], bf[2 * p + 1][0], bf[2 * p + 1][1],
                bBuf + (p * 16 * BKP + ksu * 8) * 4);
}

__global__ void __launch_bounds__(256)
gemm3_mma(const float* __restrict__ bv, float* __restrict__ out) {
    extern __shared__ float sm[];
    const uint32_t sb = smem_u32(sm);

    const int tid  = threadIdx.x;
    const int wid  = tid >> 5, lane = tid & 31;
    const int wm   = (wid >> 2) * 64;
    const int wn   = (wid & 3) * 32;
    const int lm   = lane >> 2, lk = lane & 3;
    const int n0   = blockIdx.x * BN;
    const int m0   = blockIdx.y * BM;

    const float* Arow = g_y   + (size_t)m0 * DD;
    const float* Brow = g_wvT + (size_t)n0 * DD;

    const int srow = tid >> 1;
    const int sc4  = (tid & 1) * 4;

    const int lr = lane & 7;
    const int ah = (lane >> 3) & 1;
    const int ac = lane >> 4;
    const uint32_t aAddr0 = sb + ((wm + ah * 8 + lr) * BKP + ac * 4) * 4;
    const uint32_t bAddrX4 = sb + TILE_FLOATS * 4 +
        ((wn + ((lane >> 4) & 1) * 8 + lr) * BKP + ((lane >> 3) & 1) * 4) * 4;

#define PREFETCH(S, ST) do {                                                          \
        const int k0 = (S) * BK;                                                      \
        uint32_t abase = sb + ((ST) * GSTAGE_FLOATS + srow * BKP + sc4 * 4) * 4;      \
        uint32_t bbase = abase + TILE_FLOATS * 4;                                     \
        const float* asrc = Arow + (size_t)srow * DD + k0 + sc4 * 4;                  \
        const float* bsrc = Brow + (size_t)srow * DD + k0 + sc4 * 4;                  \
        _Pragma("unroll")                                                             \
        for (int q = 0; q < 4; q++) {                                                 \
            CP_ASYNC16(abase + q * 16, asrc + q * 4);                                 \
            CP_ASYNC16(bbase + q * 16, bsrc + q * 4);                                 \
        }                                                                             \
    } while (0)

    float acc[4][4][4];
#pragma unroll
    for (int i = 0; i < 4; i++)
#pragma unroll
        for (int j = 0; j < 4; j++)
#pragma unroll
            for (int r = 0; r < 4; r++) acc[i][j][r] = 0.f;

    PREFETCH(0, 0); CP_COMMIT();
    PREFETCH(1, 1); CP_COMMIT();

    for (int s = 0; s < NSTAGE; s++) {
        const int st = s % 3;
        if (s + 2 < NSTAGE) { CP_WAIT(1); } else { CP_WAIT(0); }
        __syncthreads();
        if (s + 2 < NSTAGE) { PREFETCH(s + 2, (s + 2) % 3); CP_COMMIT(); }

        const uint32_t aBuf = aAddr0 + st * GSTAGE_FLOATS * 4;
        const uint32_t bBuf = bAddrX4 + st * GSTAGE_FLOATS * 4;

        uint32_t afr[2][4][4], bfr[2][4][2];
        ld_frags_g(afr[0], bfr[0], aBuf, bBuf, 0);
#pragma unroll
        for (int ksu = 0; ksu < 4; ksu++) {
            const int cur = ksu & 1;
            if (ksu < 3)
                ld_frags_g(afr[cur ^ 1], bfr[cur ^ 1], aBuf, bBuf, ksu + 1);
#pragma unroll
            for (int mt = 0; mt < 4; mt++)
#pragma unroll
                for (int nt = 0; nt < 4; nt++)
                    mma_tf32(acc[mt][nt], afr[cur][mt], bfr[cur][nt]);
        }
    }
#undef PREFETCH

#pragma unroll
    for (int mt = 0; mt < 4; mt++) {
        const int row = m0 + wm + mt * 16 + lm;
#pragma unroll
        for (int nt = 0; nt < 4; nt++) {
            const int col = n0 + wn + nt * 8 + 2 * lk;
            const float b0 = bv[col], b1 = bv[col + 1];
            float2 v0 = { acc[mt][nt][0] + b0, acc[mt][nt][1] + b1 };
            float2 v1 = { acc[mt][nt][2] + b0, acc[mt][nt][3] + b1 };
            *reinterpret_cast<float2*>(out + (size_t)row * DD + col) = v0;
            *reinterpret_cast<float2*>(out + (size_t)(row + 8) * DD + col) = v1;
        }
    }
}

// ---------------------------------------------------------------------------
extern "C" void kernel_launch(void* const* d_in, const int* in_sizes, int n_in,
                              void* d_out, int out_size) {
    const float*         x    = (const float*)d_in[0];
    const unsigned char* mask = (const unsigned char*)d_in[1];
    const float*         Wq   = (const float*)d_in[2];
    const float*         bq   = (const float*)d_in[3];
    const float*         Wk   = (const float*)d_in[4];
    const float*         bk   = (const float*)d_in[5];
    const float*         Wv   = (const float*)d_in[6];
    const float*         bv   = (const float*)d_in[7];
    float* out = (float*)d_out;

    wvt_kernel<<<dim3(32, 32), dim3(32, 8)>>>(Wv);
    qk_kernel<<<BB * TT / QKR, 256>>>(x, mask, Wq, bq, Wk, bk);

    const size_t asmem = ATT_SMEM_FLOATS * sizeof(float);
    cudaFuncSetAttribute(attn_kernel, cudaFuncAttributeMaxDynamicSharedMemorySize, (int)asmem);
    attn_kernel<<<dim3(TT / 64, BB), 256, asmem>>>();

    const size_t gsmem = 3 * GSTAGE_FLOATS * sizeof(float);
    cudaFuncSetAttribute(gemm3_mma, cudaFuncAttributeMaxDynamicSharedMemorySize, (int)gsmem);
    gemm3_mma<<<dim3(DD / BN, BB * TT / BM), 256, gsmem>>>(bv, out);
}